// round 12
// baseline (speedup 1.0000x reference)
#include <cuda_runtime.h>
#include <cuda_fp16.h>
#include <cstdint>

#define TT 160
#define BB 256
#define CIN 512
#define HH 256
#define GG 1024
#define RNCTA 128
#define HPITCH 136   // half2 pitch for recur smem rows (136 mod 32 == 8 -> conflict-free LDS.64)
#define IPITCH 24    // half2 pitch for igemm smem rows (24 mod 32 == 24 -> conflict-free LDS.64)

// ---------------- static scratch (no allocs allowed) ----------------
__device__ float d_XG[(size_t)TT * 2 * BB * GG];   // [T][2][B][G] input preactivations (+bias), fp32
__device__ float d_H0[(size_t)TT * BB * (2 * HH)]; // layer-0 output [T][B][512], fp32
__device__ __half d_HstS[2 * BB * HH];             // h state, fp16, pair-swizzled cols
__device__ __align__(128) unsigned d_slots[8 * 32]; // per-group barrier slots (monotonic)

// ---------------- helpers ----------------
__device__ __forceinline__ unsigned h2pack(float x, float y) {
    __half2 h = __floats2half2_rn(x, y);
    return *(unsigned*)&h;
}
__device__ __forceinline__ void mma_f16(float* c, const unsigned* a, const unsigned* b) {
    asm volatile(
        "mma.sync.aligned.m16n8k16.row.col.f32.f16.f16.f32 "
        "{%0,%1,%2,%3}, {%4,%5,%6,%7}, {%8,%9}, {%0,%1,%2,%3};"
        : "+f"(c[0]), "+f"(c[1]), "+f"(c[2]), "+f"(c[3])
        : "r"(a[0]), "r"(a[1]), "r"(a[2]), "r"(a[3]), "r"(b[0]), "r"(b[1]));
}
__device__ __forceinline__ void cp16(void* dst, const void* src) {
    unsigned d = (unsigned)__cvta_generic_to_shared(dst);
    asm volatile("cp.async.cg.shared.global [%0], [%1], 16;" ::"r"(d), "l"(src));
}
__device__ __forceinline__ float sigf(float x) { return 1.f / (1.f + __expf(-x)); }
__device__ __forceinline__ unsigned ld_acq(const unsigned* p) {
    unsigned v;
    asm volatile("ld.acquire.gpu.u32 %0, [%1];" : "=r"(v) : "l"(p));
    return v;
}
__device__ __forceinline__ void st_rel(unsigned* p, unsigned v) {
    asm volatile("st.release.gpu.u32 [%0], %1;" ::"l"(p), "r"(v));
}
// pair-swizzle on half2 index c within a group of 8 (16 halves): (c, c+4) become adjacent
__device__ __forceinline__ int pq(int c) { return ((c & 3) << 1) + ((c >> 2) & 1); }

// ---------------- slot reset kernel (graph-replay-safe barrier reuse) ----------------
__global__ void reset_kernel() { d_slots[threadIdx.x] = 0u; }

// ---------------- input GEMM (fp16 MMA): XG = A @ Wih^T + (bih+bhh), fp32 out ----------------
// CTA 128x128, BK=32 (two k16 groups), reg->smem staged fp32->fp16 conversion.
__global__ void __launch_bounds__(256) igemm_kernel(
    const float* __restrict__ Ax, int useH0,
    const float* __restrict__ Wf, const float* __restrict__ Wb,
    const float* __restrict__ bif, const float* __restrict__ bhf,
    const float* __restrict__ bib, const float* __restrict__ bhb) {
    __shared__ unsigned sA[2][128 * IPITCH];
    __shared__ unsigned sB[2][128 * IPITCH];

    const float* A = useH0 ? (const float*)d_H0 : Ax;
    const int dir = blockIdx.z;
    const float* W = dir ? Wb : Wf;
    const float* bi = dir ? bib : bif;
    const float* bh = dir ? bhb : bhf;
    const int m0 = blockIdx.y * 128;
    const int n0 = blockIdx.x * 128;
    const int tid = threadIdx.x;
    const int w = tid >> 5, lane = tid & 31;
    const int wm = w >> 2, wn = w & 3; // 2(M) x 4(N) warps, warp tile 64 x 32
    const int g_ = lane >> 2, tg = lane & 3;

    float acc[4][4][4];
#pragma unroll
    for (int i = 0; i < 4; i++)
#pragma unroll
        for (int j = 0; j < 4; j++)
#pragma unroll
            for (int q = 0; q < 4; q++) acc[i][j][q] = 0.f;

    // staging: thread -> row = tid>>1, k-group = tid&1; two 4-float chunks per i at +0,+8
    const int srow = tid >> 1;
    const int skg = tid & 1;
    float4 rA[2][2], rB[2][2];

    auto ldg_stage = [&](int k0) {
#pragma unroll
        for (int i = 0; i < 2; i++) {
            int kl = k0 + skg * 16 + i * 4;
            rA[i][0] = *(const float4*)&A[(size_t)(m0 + srow) * CIN + kl];
            rA[i][1] = *(const float4*)&A[(size_t)(m0 + srow) * CIN + kl + 8];
            rB[i][0] = *(const float4*)&W[(size_t)(n0 + srow) * CIN + kl];
            rB[i][1] = *(const float4*)&W[(size_t)(n0 + srow) * CIN + kl + 8];
        }
    };
    auto sts_stage = [&](int buf) {
#pragma unroll
        for (int i = 0; i < 2; i++) {
            int p = srow * IPITCH + skg * 8 + i * 4;
            uint2 va0 = {h2pack(rA[i][0].x, rA[i][0].y), h2pack(rA[i][1].x, rA[i][1].y)};
            uint2 va1 = {h2pack(rA[i][0].z, rA[i][0].w), h2pack(rA[i][1].z, rA[i][1].w)};
            *(uint2*)&sA[buf][p] = va0;
            *(uint2*)&sA[buf][p + 2] = va1;
            uint2 vb0 = {h2pack(rB[i][0].x, rB[i][0].y), h2pack(rB[i][1].x, rB[i][1].y)};
            uint2 vb1 = {h2pack(rB[i][0].z, rB[i][0].w), h2pack(rB[i][1].z, rB[i][1].w)};
            *(uint2*)&sB[buf][p] = vb0;
            *(uint2*)&sB[buf][p + 2] = vb1;
        }
    };

    ldg_stage(0);
    sts_stage(0);
    ldg_stage(32);
    __syncthreads();

    const int KT = CIN / 32; // 16
    for (int kt = 0; kt < KT; kt++) {
        const int buf = kt & 1;
        if (kt < KT - 1) sts_stage(buf ^ 1);
        if (kt < KT - 2) ldg_stage((kt + 2) * 32);
#pragma unroll
        for (int kg = 0; kg < 2; kg++) {
            unsigned a[4][4], b[4][2];
#pragma unroll
            for (int mt = 0; mt < 4; mt++) {
                int r = wm * 64 + mt * 16 + g_;
                uint2 lo = *(const uint2*)&sA[buf][r * IPITCH + kg * 8 + tg * 2];
                uint2 hi = *(const uint2*)&sA[buf][(r + 8) * IPITCH + kg * 8 + tg * 2];
                a[mt][0] = lo.x; a[mt][1] = hi.x; a[mt][2] = lo.y; a[mt][3] = hi.y;
            }
#pragma unroll
            for (int nt = 0; nt < 4; nt++) {
                int n = wn * 32 + nt * 8 + g_;
                uint2 bb = *(const uint2*)&sB[buf][n * IPITCH + kg * 8 + tg * 2];
                b[nt][0] = bb.x; b[nt][1] = bb.y;
            }
#pragma unroll
            for (int mt = 0; mt < 4; mt++)
#pragma unroll
                for (int nt = 0; nt < 4; nt++) mma_f16(acc[mt][nt], a[mt], b[nt]);
        }
        __syncthreads();
    }

    // epilogue: + (bih+bhh), write fp32 XG[t][dir][b][g]
#pragma unroll
    for (int mt = 0; mt < 4; mt++) {
#pragma unroll
        for (int nt = 0; nt < 4; nt++) {
            int col = n0 + wn * 32 + nt * 8 + tg * 2;
            float b0v = bi[col] + bh[col];
            float b1v = bi[col + 1] + bh[col + 1];
#pragma unroll
            for (int hh = 0; hh < 2; hh++) {
                int row = m0 + wm * 64 + mt * 16 + g_ + hh * 8;
                int tt = row >> 8, bb = row & 255;
                float2 v;
                v.x = acc[mt][nt][hh * 2 + 0] + b0v;
                v.y = acc[mt][nt][hh * 2 + 1] + b1v;
                *(float2*)&d_XG[(((size_t)tt * 2 + dir) * BB + bb) * GG + col] = v;
            }
        }
    }
}

// ---------------- persistent recurrence kernel (fp16 MMA, register pointwise) ----------------
// 128 CTAs: (dir, btile, jg). CTA owns b rows [b0,b0+64), gate cols {q*256+j0..+15 | q=0..3}.
// ws rows n are gate-interleaved: q = ((n>>3)&1)*2 + (n&1), jj = ((n>>4)&3)*4 + ((n>>1)&3),
// so each thread's MMA fragment holds all 4 gates for 4 complete LSTM cells -> no exchange.
#define SMEMREC (2 * 64 * HPITCH * 4)

__global__ void __launch_bounds__(256) recur_kernel(
    const float* __restrict__ Whf, const float* __restrict__ Whb,
    float* __restrict__ outp, int writeOut) {
    extern __shared__ unsigned smu[];
    unsigned* ws = smu;                // [64][HPITCH] half2: gate-interleaved, swizzled Whh
    unsigned* hs = smu + 64 * HPITCH;  // [64][HPITCH] half2: h tile (swizzled)

    const int cta = blockIdx.x;
    const int tid = threadIdx.x;
    const int dir = cta >> 6;
    const int sub = cta & 63;
    const int btile = sub >> 4;
    const int jg = sub & 15;
    const int b0 = btile * 64;
    const int j0 = jg * 16;
    const float* Wh = dir ? Whb : Whf;
    float* outb = writeOut ? outp : (float*)d_H0;
    unsigned* slots = &d_slots[(dir * 4 + btile) * 32];

    const int w = tid >> 5, lane = tid & 31;
    const int wm = w >> 2, wn = w & 3; // 2(M) x 4(N) warps; warp tile 32 x 16
    const int g_ = lane >> 2, tg = lane & 3;

    // --- build gate-interleaved weight slice, fp16 + pair-swizzled
    {
        int r = tid >> 2;                 // 0..63
        int q = ((r >> 3) & 1) * 2 + (r & 1);
        int jj = ((r >> 4) & 3) * 4 + ((r >> 1) & 3);
        const float* wrow = &Wh[(size_t)(q * 256 + j0 + jj) * HH];
#pragma unroll
        for (int c2 = 0; c2 < 32; c2++) {
            int c = (tid & 3) * 32 + c2;  // half2 index 0..127
            unsigned v = h2pack(wrow[c * 2], wrow[c * 2 + 1]);
            ws[r * HPITCH + (c & ~7) + pq(c & 7)] = v;
        }
    }

    // --- this thread's 4 cells: rows (mt,hh), col j = j0 + wn*4 + tg
    const int jloc = wn * 4 + tg;
    const int j = j0 + jloc;
    const int cc = (j >> 1) & 7;
    const int spos = (j & ~15) + pq(cc) * 2 + (j & 1); // swizzled half index within 256
    float cst[2][2] = {{0.f, 0.f}, {0.f, 0.f}};

    // h0 = 0 (state is fp16-swizzled; zeros are position-independent but use exact addr anyway)
#pragma unroll
    for (int mt = 0; mt < 2; mt++)
#pragma unroll
        for (int hh = 0; hh < 2; hh++) {
            int row = b0 + wm * 32 + mt * 16 + g_ + hh * 8;
            d_HstS[(size_t)(dir * BB + row) * HH + spos] = __float2half(0.f);
        }

    // --- XG prefetch registers (gate-strided scalar loads)
    float xgr[2][2][2][2];
    auto prefetchXG = [&](int s) {
        int t = dir ? (TT - 1 - s) : s;
        const float* base = d_XG + ((size_t)t * 2 + dir) * BB * GG;
#pragma unroll
        for (int mt = 0; mt < 2; mt++)
#pragma unroll
            for (int nt = 0; nt < 2; nt++)
#pragma unroll
                for (int hh = 0; hh < 2; hh++)
#pragma unroll
                    for (int u = 0; u < 2; u++) {
                        int row = b0 + wm * 32 + mt * 16 + g_ + hh * 8;
                        int gcol = (nt * 2 + u) * 256 + j0 + jloc;
                        xgr[mt][nt][hh][u] = __ldcg(&base[(size_t)row * GG + gcol]);
                    }
    };
    prefetchXG(0);

    // announce h0 ready
    __syncthreads();
    if (tid == 0) st_rel(&slots[jg], 1u);

    for (int s = 0; s < TT; s++) {
        const int t = dir ? (TT - 1 - s) : s;

        // --- wait for all 16 group peers at step s
        if (tid < 16) {
            unsigned v;
            do { v = ld_acq(&slots[tid]); } while (__any_sync(0x0000ffffu, v < (unsigned)(s + 1)));
        }
        __syncthreads();

        // --- h tile fill via cp.async (already fp16 + swizzled), 2 k-halves
#pragma unroll
        for (int ph = 0; ph < 2; ph++) {
#pragma unroll
            for (int i = 0; i < 4; i++) {
                int c = tid + i * 256;       // 0..1023 chunk id (16B)
                int r = c >> 4, ch = c & 15;
                cp16(&hs[r * HPITCH + ph * 64 + ch * 4],
                     &d_HstS[(size_t)(dir * BB + b0 + r) * HH + ph * 128 + ch * 8]);
            }
            asm volatile("cp.async.commit_group;");
        }

        float acc[2][2][4];
#pragma unroll
        for (int i = 0; i < 2; i++)
#pragma unroll
            for (int jx = 0; jx < 2; jx++)
#pragma unroll
                for (int q = 0; q < 4; q++) acc[i][jx][q] = 0.f;

        asm volatile("cp.async.wait_group 1;");
        __syncthreads();

#pragma unroll
        for (int ph = 0; ph < 2; ph++) {
#pragma unroll 8
            for (int k16 = ph * 8; k16 < ph * 8 + 8; k16++) {
                const int off = k16 * 8 + tg * 2;
                unsigned a[2][4], b[2][2];
#pragma unroll
                for (int mt = 0; mt < 2; mt++) {
                    int r = wm * 32 + mt * 16 + g_;
                    uint2 lo = *(const uint2*)&hs[r * HPITCH + off];
                    uint2 hi = *(const uint2*)&hs[(r + 8) * HPITCH + off];
                    a[mt][0] = lo.x; a[mt][1] = hi.x; a[mt][2] = lo.y; a[mt][3] = hi.y;
                }
#pragma unroll
                for (int nt = 0; nt < 2; nt++) {
                    int n = wn * 16 + nt * 8 + g_;
                    uint2 bb = *(const uint2*)&ws[n * HPITCH + off];
                    b[nt][0] = bb.x; b[nt][1] = bb.y;
                }
#pragma unroll
                for (int mt = 0; mt < 2; mt++)
#pragma unroll
                    for (int nt = 0; nt < 2; nt++) mma_f16(acc[mt][nt], a[mt], b[nt]);
            }
            if (ph == 0) {
                asm volatile("cp.async.wait_group 0;");
                __syncthreads();
            }
        }

        // --- fused pointwise, all in registers (acc holds i,f,g,o per cell)
#pragma unroll
        for (int mt = 0; mt < 2; mt++)
#pragma unroll
            for (int hh = 0; hh < 2; hh++) {
                int row = b0 + wm * 32 + mt * 16 + g_ + hh * 8;
                float gi = acc[mt][0][hh * 2 + 0] + xgr[mt][0][hh][0];
                float gf = acc[mt][0][hh * 2 + 1] + xgr[mt][0][hh][1];
                float gc = acc[mt][1][hh * 2 + 0] + xgr[mt][1][hh][0];
                float go = acc[mt][1][hh * 2 + 1] + xgr[mt][1][hh][1];
                float cn = sigf(gf) * cst[mt][hh] + sigf(gi) * tanhf(gc);
                cst[mt][hh] = cn;
                float hv = sigf(go) * tanhf(cn);
                outb[((size_t)t * BB + row) * (2 * HH) + dir * HH + j] = hv;
                d_HstS[(size_t)(dir * BB + row) * HH + spos] = __float2half_rn(hv);
            }

        if (s + 1 < TT) prefetchXG(s + 1); // overlaps fence + peers' waits

        __syncthreads();
        if (tid == 0) st_rel(&slots[jg], (unsigned)(s + 2));
    }
}

// ---------------- launch ----------------
extern "C" void kernel_launch(void* const* d_in, const int* in_sizes, int n_in,
                              void* d_out, int out_size) {
    (void)in_sizes; (void)n_in; (void)out_size;
    const float* x = (const float*)d_in[0];
    const float* wih0f = (const float*)d_in[1];
    const float* whh0f = (const float*)d_in[2];
    const float* bih0f = (const float*)d_in[3];
    const float* bhh0f = (const float*)d_in[4];
    const float* wih0b = (const float*)d_in[5];
    const float* whh0b = (const float*)d_in[6];
    const float* bih0b = (const float*)d_in[7];
    const float* bhh0b = (const float*)d_in[8];
    const float* wih1f = (const float*)d_in[9];
    const float* whh1f = (const float*)d_in[10];
    const float* bih1f = (const float*)d_in[11];
    const float* bhh1f = (const float*)d_in[12];
    const float* wih1b = (const float*)d_in[13];
    const float* whh1b = (const float*)d_in[14];
    const float* bih1b = (const float*)d_in[15];
    const float* bhh1b = (const float*)d_in[16];
    float* out = (float*)d_out;

    cudaFuncSetAttribute(recur_kernel, cudaFuncAttributeMaxDynamicSharedMemorySize, SMEMREC);

    dim3 gg(GG / 128, (TT * BB) / 128, 2); // (8, 320, 2)

    reset_kernel<<<1, 256>>>();
    igemm_kernel<<<gg, 256>>>(x, 0, wih0f, wih0b, bih0f, bhh0f, bih0b, bhh0b);
    recur_kernel<<<RNCTA, 256, SMEMREC>>>(whh0f, whh0b, nullptr, 0);
    reset_kernel<<<1, 256>>>();
    igemm_kernel<<<gg, 256>>>(nullptr, 1, wih1f, wih1b, bih1f, bhh1f, bih1b, bhh1b);
    recur_kernel<<<RNCTA, 256, SMEMREC>>>(whh1f, whh1b, out, 1);
}